// round 11
// baseline (speedup 1.0000x reference)
#include <cuda_runtime.h>
#include <cuda_bf16.h>
#include <cstdint>
#include <math.h>

#define BDIM   4096
#define INDIM  256
#define OUTDIM 256
#define NC     8
#define KDIM   (INDIM * NC)      // 2048
#define KSPLIT 2
#define KHALF  (KDIM / KSPLIT)   // 1024

// ---------------- scratch (static device globals; no allocations) ----------
__device__ __nv_bfloat16 g_Bh[(size_t)OUTDIM * KDIM];      //  1 MB  B, [o][k]
__device__ __nv_bfloat16 g_A[(size_t)BDIM * KDIM];         // 16 MB  A, [b][k]
__device__ float g_part[(size_t)KSPLIT * BDIM * OUTDIM];   //  8 MB  partials
__device__ float g_rv[BDIM];                               // residual sums

// ---------------------------------------------------------------------------
// 1) merged build: blocks 0..255 build W^T, blocks 256..4351 build A + rv
// ---------------------------------------------------------------------------
__global__ __launch_bounds__(256) void build_AW_kernel(
    const float* __restrict__ coefs, const float* __restrict__ spline_scale,
    const float* __restrict__ x, const float* __restrict__ resid_scale,
    const float* __restrict__ aat) {
    const int tid = threadIdx.x;
    const int blk = blockIdx.x;

    if (blk < 256) {
        // ---- W: g_Bh[o][i*8+c] = bf16(spline_scale[i,o]*coefs[i,o,c]) ----
        int idx = blk * 256 + tid;  // i*256 + o
        int i = idx >> 8, o = idx & 255;
        float ss = spline_scale[idx];
        const float* cf = coefs + (size_t)idx * NC;
        uint4 uh;
        uint32_t* ph = (uint32_t*)&uh;
#pragma unroll
        for (int c = 0; c < 4; c++) {
            __nv_bfloat162 t = __floats2bfloat162_rn(ss * cf[2 * c], ss * cf[2 * c + 1]);
            ph[c] = *(uint32_t*)&t;
        }
        *(uint4*)&g_Bh[(size_t)o * KDIM + i * NC] = uh;
        return;
    }

    // ---- A: g_A[b][i*8+c] = bf16(P_c(tanh(x[b,i]))),  rv[b] ----
    const int b = blk - 256;
    const int i = tid;

    const float alpha = tanhf(__ldg(aat));
    float r1[NC], r2[NC];
#pragma unroll
    for (int n = 2; n < NC; n++) {
        float c = 2.0f * n + 2.0f * alpha;
        float A = 2.0f * n * (n + 2.0f * alpha) * (c - 2.0f);
        r1[n] = (c - 1.0f) * c * (c - 2.0f) / A;
        r2[n] = 2.0f * (n + alpha - 1.0f) * (n + alpha - 1.0f) * c / A;
    }

    float t = tanhf(x[(size_t)b * INDIM + i]);

    float pr[NC];
    pr[0] = 1.0f;
    pr[1] = (alpha + 1.0f) + (alpha + alpha + 2.0f) * (t - 1.0f) * 0.5f;
#pragma unroll
    for (int n = 2; n < NC; n++)
        pr[n] = r1[n] * t * pr[n - 1] - r2[n] * pr[n - 2];

    uint4 uh;
    uint32_t* ph = (uint32_t*)&uh;
#pragma unroll
    for (int c = 0; c < 4; c++) {
        __nv_bfloat162 t2 = __floats2bfloat162_rn(pr[2 * c], pr[2 * c + 1]);
        ph[c] = *(uint32_t*)&t2;
    }
    *(uint4*)&g_A[(size_t)b * KDIM + i * NC] = uh;

    // rv reduction over 256 i's
    float rt = resid_scale[i] * t;
#pragma unroll
    for (int off = 16; off > 0; off >>= 1)
        rt += __shfl_down_sync(0xffffffffu, rt, off);
    __shared__ float sred[8];
    if ((tid & 31) == 0) sred[tid >> 5] = rt;
    __syncthreads();
    if (tid < 8) {
        float v = sred[tid];
#pragma unroll
        for (int off = 4; off > 0; off >>= 1)
            v += __shfl_down_sync(0xffu, v, off);
        if (tid == 0) g_rv[b] = v;
    }
}

// ---------------------------------------------------------------------------
// 2) GEMM, single-pass bf16, split-K=2 — pure feed inner loop
//    CTA 64x64, BK=64, 128 threads (4 warps, warp tile 32x32)
//    A and B: 3-deep cp.async rings, ONE __syncthreads per stage
// ---------------------------------------------------------------------------
#define BM 64
#define BN 64
#define BK 64
#define NTS (KHALF / BK)        // 16 k-chunks per split

#define ROWB 144                // 128B data + 16B pad
#define TILE_B (64 * ROWB)      // 9216 per tile
// layout: A0..A2 @0..2*TILE_B, B0..B2 @3..5*TILE_B
#define GEMM_SMEM (6 * TILE_B)  // 55296

__device__ __forceinline__ uint32_t smem_u32(const void* p) {
    uint32_t a;
    asm("{ .reg .u64 t; cvta.to.shared.u64 t, %1; cvt.u32.u64 %0, t; }"
        : "=r"(a) : "l"(p));
    return a;
}
__device__ __forceinline__ void cp16(uint32_t s, const void* g) {
    asm volatile("cp.async.cg.shared.global [%0], [%1], 16;" :: "r"(s), "l"(g));
}
__device__ __forceinline__ void ldsm_x4(uint32_t* r, uint32_t addr) {
    asm volatile("ldmatrix.sync.aligned.m8n8.x4.shared.b16 {%0,%1,%2,%3}, [%4];"
                 : "=r"(r[0]), "=r"(r[1]), "=r"(r[2]), "=r"(r[3]) : "r"(addr));
}
__device__ __forceinline__ void mma_bf16(float* d, const uint32_t* a, const uint32_t* b) {
    asm volatile(
        "mma.sync.aligned.m16n8k16.row.col.f32.bf16.bf16.f32 "
        "{%0,%1,%2,%3}, {%4,%5,%6,%7}, {%8,%9}, {%0,%1,%2,%3};"
        : "+f"(d[0]), "+f"(d[1]), "+f"(d[2]), "+f"(d[3])
        : "r"(a[0]), "r"(a[1]), "r"(a[2]), "r"(a[3]), "r"(b[0]), "r"(b[1]));
}

// prefetch A(kt) and B(kt) into ring slot (one commit group)
__device__ __forceinline__ void prefetch_AB(uint32_t sb, int slot, int kt,
                                            int m0, int n0, int z, int tid) {
    const int k0 = z * KHALF + kt * BK;
    const uint32_t dstA = sb + slot * TILE_B;
    const uint32_t dstB = sb + (3 + slot) * TILE_B;
#pragma unroll
    for (int p = 0; p < 4; ++p) {
        int idx = p * 128 + tid;           // 0..511
        int r = idx >> 3, c = idx & 7;
        cp16(dstA + r * ROWB + c * 16,
             g_A + (size_t)(m0 + r) * KDIM + k0 + c * 8);
        cp16(dstB + r * ROWB + c * 16,
             g_Bh + (size_t)(n0 + r) * KDIM + k0 + c * 8);
    }
    asm volatile("cp.async.commit_group;" ::: "memory");
}

__global__ __launch_bounds__(128, 4) void gemm_tc(
    const float* __restrict__ x_unused) {
    extern __shared__ char smem[];
    const int tid  = threadIdx.x;
    const int wid  = tid >> 5;
    const int lane = tid & 31;
    const int m0   = blockIdx.x * BM;
    const int n0   = blockIdx.y * BN;
    const int z    = blockIdx.z;
    const int mbase = (wid & 1) * 32;
    const int nbase = (wid >> 1) * 32;
    const uint32_t sb = smem_u32(smem);

    float acc[2][4][4];
#pragma unroll
    for (int i = 0; i < 2; i++)
#pragma unroll
        for (int j = 0; j < 4; j++)
#pragma unroll
            for (int r = 0; r < 4; r++) acc[i][j][r] = 0.0f;

    // ldmatrix per-lane address pieces (mapping verified R3-R10)
    const int g  = lane >> 3;
    const int lr = lane & 7;
    const int a_row_off = lr + ((g & 1) ? 8 : 0);
    const int kb_off    = (g >= 2) ? 16 : 0;

    // prologue: stages 0 and 1
    prefetch_AB(sb, 0, 0, m0, n0, z, tid);
    prefetch_AB(sb, 1, 1, m0, n0, z, tid);
    asm volatile("cp.async.wait_group 1;" ::: "memory");
    __syncthreads();

#pragma unroll 4
    for (int kt = 0; kt < NTS; ++kt) {
        const int slot = kt % 3;
        const uint32_t stA = sb + slot * TILE_B;
        const uint32_t stB = sb + (3 + slot) * TILE_B;

        // ---- MMA phase on ring slot ----
#pragma unroll
        for (int ks = 0; ks < 4; ++ks) {
            uint32_t a[2][4], b[4][2];
#pragma unroll
            for (int mf = 0; mf < 2; ++mf) {
                uint32_t row = mbase + mf * 16 + a_row_off;
                ldsm_x4(a[mf], stA + row * ROWB + ks * 32 + kb_off);
            }
#pragma unroll
            for (int np = 0; np < 2; ++np) {
                uint32_t row = nbase + np * 16 + lr + ((g >= 2) ? 8 : 0);
                uint32_t kb2 = ks * 32 + ((g & 1) ? 16 : 0);
                uint32_t r4[4];
                ldsm_x4(r4, stB + row * ROWB + kb2);
                b[2 * np][0] = r4[0];     b[2 * np][1] = r4[1];
                b[2 * np + 1][0] = r4[2]; b[2 * np + 1][1] = r4[3];
            }
#pragma unroll
            for (int mf = 0; mf < 2; ++mf)
#pragma unroll
                for (int nf = 0; nf < 4; ++nf)
                    mma_bf16(acc[mf][nf], a[mf], b[nf]);
        }

        // ---- prefetch kt+2 into slot (kt+2)%3 (last read at kt-1; safe) ----
        if (kt + 2 < NTS) {
            prefetch_AB(sb, (kt + 2) % 3, kt + 2, m0, n0, z, tid);
            asm volatile("cp.async.wait_group 1;" ::: "memory");  // kt+1 done
        } else if (kt + 1 < NTS) {
            asm volatile("cp.async.wait_group 0;" ::: "memory");
        }

        if (kt + 1 < NTS) __syncthreads();   // single barrier per stage
    }

    // write partial tile
    float* dst = g_part + (size_t)z * BDIM * OUTDIM;
    const int l4 = lane >> 2, l2 = (lane & 3) * 2;
#pragma unroll
    for (int mf = 0; mf < 2; ++mf) {
        int m = m0 + mbase + mf * 16 + l4;
#pragma unroll
        for (int nf = 0; nf < 4; ++nf) {
            int n = n0 + nbase + nf * 8 + l2;
            *(float2*)&dst[(size_t)m * OUTDIM + n] =
                make_float2(acc[mf][nf][0], acc[mf][nf][1]);
            *(float2*)&dst[(size_t)(m + 8) * OUTDIM + n] =
                make_float2(acc[mf][nf][2], acc[mf][nf][3]);
        }
    }
}

// ---------------------------------------------------------------------------
// 3) combine: out = (part0 + part1 + rv) / IN
// ---------------------------------------------------------------------------
__global__ __launch_bounds__(256) void combine_kernel(float* __restrict__ out) {
    int idx = blockIdx.x * 256 + threadIdx.x;   // float4 index
    int m = idx >> 6, c4 = (idx & 63) * 4;
    size_t o0 = (size_t)m * OUTDIM + c4;
    float4 a = *(float4*)&g_part[o0];
    float4 b = *(float4*)&g_part[(size_t)BDIM * OUTDIM + o0];
    float rv = g_rv[m];
    const float s = 1.0f / (float)INDIM;
    float4 o;
    o.x = (a.x + b.x + rv) * s;
    o.y = (a.y + b.y + rv) * s;
    o.z = (a.z + b.z + rv) * s;
    o.w = (a.w + b.w + rv) * s;
    *(float4*)&out[o0] = o;
}

// ---------------------------------------------------------------------------
extern "C" void kernel_launch(void* const* d_in, const int* in_sizes, int n_in,
                              void* d_out, int out_size) {
    const float *x = nullptr, *coefs = nullptr, *aat = nullptr;
    const float *resid_scale = nullptr, *spline_scale = nullptr;
    for (int i = 0; i < n_in; i++) {
        switch (in_sizes[i]) {
            case BDIM * INDIM:        x            = (const float*)d_in[i]; break;
            case INDIM * OUTDIM * NC: coefs        = (const float*)d_in[i]; break;
            case 1:                   aat          = (const float*)d_in[i]; break;
            case INDIM:               resid_scale  = (const float*)d_in[i]; break;
            case INDIM * OUTDIM:      spline_scale = (const float*)d_in[i]; break;
            default: break;
        }
    }
    float* out = (float*)d_out;

    cudaFuncSetAttribute(gemm_tc, cudaFuncAttributeMaxDynamicSharedMemorySize, GEMM_SMEM);

    build_AW_kernel<<<256 + BDIM, 256>>>(coefs, spline_scale, x, resid_scale, aat);
    dim3 grid(BDIM / BM, OUTDIM / BN, KSPLIT);
    gemm_tc<<<grid, 128, GEMM_SMEM>>>(x);
    combine_kernel<<<(BDIM * OUTDIM / 4) / 256, 256>>>(out);
}

// round 12
// speedup vs baseline: 1.1356x; 1.1356x over previous
#include <cuda_runtime.h>
#include <cuda_bf16.h>
#include <cstdint>
#include <math.h>

#define BDIM   4096
#define INDIM  256
#define OUTDIM 256
#define NC     8
#define KDIM   (INDIM * NC)      // 2048
#define KSPLIT 2
#define KHALF  (KDIM / KSPLIT)   // 1024
#define BPB    8                 // batch rows per build-thread

// ---------------- scratch (static device globals; no allocations) ----------
__device__ __nv_bfloat16 g_Bh[(size_t)OUTDIM * KDIM];      //  1 MB  B, [o][k]
__device__ __nv_bfloat16 g_A[(size_t)BDIM * KDIM];         // 16 MB  A, [b][k]
__device__ float g_part[(size_t)KSPLIT * BDIM * OUTDIM];   //  8 MB  partials
__device__ float g_rv[BDIM];                               // residual sums

// ---------------------------------------------------------------------------
// 1) merged build: blocks 0..255 build W^T; blocks 256..767 build A + rv
//    (each A-thread handles BPB=8 batch rows => coeff cost amortized)
// ---------------------------------------------------------------------------
__global__ __launch_bounds__(256) void build_AW_kernel(
    const float* __restrict__ coefs, const float* __restrict__ spline_scale,
    const float* __restrict__ x, const float* __restrict__ resid_scale,
    const float* __restrict__ aat) {
    const int tid = threadIdx.x;
    const int blk = blockIdx.x;

    if (blk < 256) {
        // ---- W: g_Bh[o][i*8+c] = bf16(spline_scale[i,o]*coefs[i,o,c]) ----
        int idx = blk * 256 + tid;  // i*256 + o
        int i = idx >> 8, o = idx & 255;
        float ss = spline_scale[idx];
        const float* cf = coefs + (size_t)idx * NC;
        uint4 uh;
        uint32_t* ph = (uint32_t*)&uh;
#pragma unroll
        for (int c = 0; c < 4; c++) {
            __nv_bfloat162 t = __floats2bfloat162_rn(ss * cf[2 * c], ss * cf[2 * c + 1]);
            ph[c] = *(uint32_t*)&t;
        }
        *(uint4*)&g_Bh[(size_t)o * KDIM + i * NC] = uh;
        return;
    }

    // ---- A: thread (blk,i=tid) handles b = b0..b0+7 of column i ----
    const int b0 = (blk - 256) * BPB;
    const int i  = tid;

    // x loads first (MLP=8 hides latency under the coeff computation)
    float xv[BPB];
#pragma unroll
    for (int p = 0; p < BPB; ++p)
        xv[p] = x[(size_t)(b0 + p) * INDIM + i];

    const float alpha = tanhf(__ldg(aat));
    float r1[NC], r2[NC];
#pragma unroll
    for (int n = 2; n < NC; n++) {
        float c = 2.0f * n + 2.0f * alpha;
        float A = 2.0f * n * (n + 2.0f * alpha) * (c - 2.0f);
        r1[n] = (c - 1.0f) * c * (c - 2.0f) / A;
        r2[n] = 2.0f * (n + alpha - 1.0f) * (n + alpha - 1.0f) * c / A;
    }
    const float rs = resid_scale[i];

    float rt[BPB];
#pragma unroll
    for (int p = 0; p < BPB; ++p) {
        float t = tanhf(xv[p]);
        rt[p] = rs * t;

        float pr[NC];
        pr[0] = 1.0f;
        pr[1] = (alpha + 1.0f) + (alpha + alpha + 2.0f) * (t - 1.0f) * 0.5f;
#pragma unroll
        for (int n = 2; n < NC; n++)
            pr[n] = r1[n] * t * pr[n - 1] - r2[n] * pr[n - 2];

        uint4 uh;
        uint32_t* ph = (uint32_t*)&uh;
#pragma unroll
        for (int c = 0; c < 4; c++) {
            __nv_bfloat162 t2 = __floats2bfloat162_rn(pr[2 * c], pr[2 * c + 1]);
            ph[c] = *(uint32_t*)&t2;
        }
        *(uint4*)&g_A[(size_t)(b0 + p) * KDIM + i * NC] = uh;
    }

    // rv reductions: for each p, sum rt[p] over the 256 i's of this block
    __shared__ float sred[8][BPB];    // [warp][p]
    const int wid = tid >> 5;
#pragma unroll
    for (int p = 0; p < BPB; ++p) {
        float v = rt[p];
#pragma unroll
        for (int off = 16; off > 0; off >>= 1)
            v += __shfl_down_sync(0xffffffffu, v, off);
        if ((tid & 31) == 0) sred[wid][p] = v;
    }
    __syncthreads();
    if (tid < BPB) {
        float v = 0.0f;
#pragma unroll
        for (int w = 0; w < 8; ++w) v += sred[w][tid];
        g_rv[b0 + tid] = v;
    }
}

// ---------------------------------------------------------------------------
// 2) GEMM, single-pass bf16, split-K=2 — pure feed inner loop (R11-proven)
//    CTA 64x64, BK=64, 128 threads (4 warps, warp tile 32x32)
//    A and B: 3-deep cp.async rings, ONE __syncthreads per stage
// ---------------------------------------------------------------------------
#define BM 64
#define BN 64
#define BK 64
#define NTS (KHALF / BK)        // 16 k-chunks per split

#define ROWB 144                // 128B data + 16B pad
#define TILE_B (64 * ROWB)      // 9216 per tile
// layout: A0..A2 @0..2*TILE_B, B0..B2 @3..5*TILE_B
#define GEMM_SMEM (6 * TILE_B)  // 55296

__device__ __forceinline__ uint32_t smem_u32(const void* p) {
    uint32_t a;
    asm("{ .reg .u64 t; cvta.to.shared.u64 t, %1; cvt.u32.u64 %0, t; }"
        : "=r"(a) : "l"(p));
    return a;
}
__device__ __forceinline__ void cp16(uint32_t s, const void* g) {
    asm volatile("cp.async.cg.shared.global [%0], [%1], 16;" :: "r"(s), "l"(g));
}
__device__ __forceinline__ void ldsm_x4(uint32_t* r, uint32_t addr) {
    asm volatile("ldmatrix.sync.aligned.m8n8.x4.shared.b16 {%0,%1,%2,%3}, [%4];"
                 : "=r"(r[0]), "=r"(r[1]), "=r"(r[2]), "=r"(r[3]) : "r"(addr));
}
__device__ __forceinline__ void mma_bf16(float* d, const uint32_t* a, const uint32_t* b) {
    asm volatile(
        "mma.sync.aligned.m16n8k16.row.col.f32.bf16.bf16.f32 "
        "{%0,%1,%2,%3}, {%4,%5,%6,%7}, {%8,%9}, {%0,%1,%2,%3};"
        : "+f"(d[0]), "+f"(d[1]), "+f"(d[2]), "+f"(d[3])
        : "r"(a[0]), "r"(a[1]), "r"(a[2]), "r"(a[3]), "r"(b[0]), "r"(b[1]));
}

// prefetch A(kt) and B(kt) into ring slot (one commit group)
__device__ __forceinline__ void prefetch_AB(uint32_t sb, int slot, int kt,
                                            int m0, int n0, int z, int tid) {
    const int k0 = z * KHALF + kt * BK;
    const uint32_t dstA = sb + slot * TILE_B;
    const uint32_t dstB = sb + (3 + slot) * TILE_B;
#pragma unroll
    for (int p = 0; p < 4; ++p) {
        int idx = p * 128 + tid;           // 0..511
        int r = idx >> 3, c = idx & 7;
        cp16(dstA + r * ROWB + c * 16,
             g_A + (size_t)(m0 + r) * KDIM + k0 + c * 8);
        cp16(dstB + r * ROWB + c * 16,
             g_Bh + (size_t)(n0 + r) * KDIM + k0 + c * 8);
    }
    asm volatile("cp.async.commit_group;" ::: "memory");
}

__global__ __launch_bounds__(128, 4) void gemm_tc() {
    extern __shared__ char smem[];
    const int tid  = threadIdx.x;
    const int wid  = tid >> 5;
    const int lane = tid & 31;
    const int m0   = blockIdx.x * BM;
    const int n0   = blockIdx.y * BN;
    const int z    = blockIdx.z;
    const int mbase = (wid & 1) * 32;
    const int nbase = (wid >> 1) * 32;
    const uint32_t sb = smem_u32(smem);

    float acc[2][4][4];
#pragma unroll
    for (int i = 0; i < 2; i++)
#pragma unroll
        for (int j = 0; j < 4; j++)
#pragma unroll
            for (int r = 0; r < 4; r++) acc[i][j][r] = 0.0f;

    // ldmatrix per-lane address pieces (mapping verified R3-R11)
    const int g  = lane >> 3;
    const int lr = lane & 7;
    const int a_row_off = lr + ((g & 1) ? 8 : 0);
    const int kb_off    = (g >= 2) ? 16 : 0;

    // prologue: stages 0 and 1
    prefetch_AB(sb, 0, 0, m0, n0, z, tid);
    prefetch_AB(sb, 1, 1, m0, n0, z, tid);
    asm volatile("cp.async.wait_group 1;" ::: "memory");
    __syncthreads();

#pragma unroll 4
    for (int kt = 0; kt < NTS; ++kt) {
        const int slot = kt % 3;
        const uint32_t stA = sb + slot * TILE_B;
        const uint32_t stB = sb + (3 + slot) * TILE_B;

        // ---- MMA phase on ring slot ----
#pragma unroll
        for (int ks = 0; ks < 4; ++ks) {
            uint32_t a[2][4], b[4][2];
#pragma unroll
            for (int mf = 0; mf < 2; ++mf) {
                uint32_t row = mbase + mf * 16 + a_row_off;
                ldsm_x4(a[mf], stA + row * ROWB + ks * 32 + kb_off);
            }
#pragma unroll
            for (int np = 0; np < 2; ++np) {
                uint32_t row = nbase + np * 16 + lr + ((g >= 2) ? 8 : 0);
                uint32_t kb2 = ks * 32 + ((g & 1) ? 16 : 0);
                uint32_t r4[4];
                ldsm_x4(r4, stB + row * ROWB + kb2);
                b[2 * np][0] = r4[0];     b[2 * np][1] = r4[1];
                b[2 * np + 1][0] = r4[2]; b[2 * np + 1][1] = r4[3];
            }
#pragma unroll
            for (int mf = 0; mf < 2; ++mf)
#pragma unroll
                for (int nf = 0; nf < 4; ++nf)
                    mma_bf16(acc[mf][nf], a[mf], b[nf]);
        }

        // ---- prefetch kt+2 into slot (kt+2)%3 (last read at kt-1; safe) ----
        if (kt + 2 < NTS) {
            prefetch_AB(sb, (kt + 2) % 3, kt + 2, m0, n0, z, tid);
            asm volatile("cp.async.wait_group 1;" ::: "memory");  // kt+1 done
        } else if (kt + 1 < NTS) {
            asm volatile("cp.async.wait_group 0;" ::: "memory");
        }

        if (kt + 1 < NTS) __syncthreads();   // single barrier per stage
    }

    // write partial tile
    float* dst = g_part + (size_t)z * BDIM * OUTDIM;
    const int l4 = lane >> 2, l2 = (lane & 3) * 2;
#pragma unroll
    for (int mf = 0; mf < 2; ++mf) {
        int m = m0 + mbase + mf * 16 + l4;
#pragma unroll
        for (int nf = 0; nf < 4; ++nf) {
            int n = n0 + nbase + nf * 8 + l2;
            *(float2*)&dst[(size_t)m * OUTDIM + n] =
                make_float2(acc[mf][nf][0], acc[mf][nf][1]);
            *(float2*)&dst[(size_t)(m + 8) * OUTDIM + n] =
                make_float2(acc[mf][nf][2], acc[mf][nf][3]);
        }
    }
}

// ---------------------------------------------------------------------------
// 3) combine: out = (part0 + part1 + rv) / IN
// ---------------------------------------------------------------------------
__global__ __launch_bounds__(256) void combine_kernel(float* __restrict__ out) {
    int idx = blockIdx.x * 256 + threadIdx.x;   // float4 index
    int m = idx >> 6, c4 = (idx & 63) * 4;
    size_t o0 = (size_t)m * OUTDIM + c4;
    float4 a = *(float4*)&g_part[o0];
    float4 b = *(float4*)&g_part[(size_t)BDIM * OUTDIM + o0];
    float rv = g_rv[m];
    const float s = 1.0f / (float)INDIM;
    float4 o;
    o.x = (a.x + b.x + rv) * s;
    o.y = (a.y + b.y + rv) * s;
    o.z = (a.z + b.z + rv) * s;
    o.w = (a.w + b.w + rv) * s;
    *(float4*)&out[o0] = o;
}

// ---------------------------------------------------------------------------
extern "C" void kernel_launch(void* const* d_in, const int* in_sizes, int n_in,
                              void* d_out, int out_size) {
    const float *x = nullptr, *coefs = nullptr, *aat = nullptr;
    const float *resid_scale = nullptr, *spline_scale = nullptr;
    for (int i = 0; i < n_in; i++) {
        switch (in_sizes[i]) {
            case BDIM * INDIM:        x            = (const float*)d_in[i]; break;
            case INDIM * OUTDIM * NC: coefs        = (const float*)d_in[i]; break;
            case 1:                   aat          = (const float*)d_in[i]; break;
            case INDIM:               resid_scale  = (const float*)d_in[i]; break;
            case INDIM * OUTDIM:      spline_scale = (const float*)d_in[i]; break;
            default: break;
        }
    }
    float* out = (float*)d_out;

    cudaFuncSetAttribute(gemm_tc, cudaFuncAttributeMaxDynamicSharedMemorySize, GEMM_SMEM);

    build_AW_kernel<<<256 + BDIM / BPB, 256>>>(coefs, spline_scale, x, resid_scale, aat);
    dim3 grid(BDIM / BM, OUTDIM / BN, KSPLIT);
    gemm_tc<<<grid, 128, GEMM_SMEM>>>();
    combine_kernel<<<(BDIM * OUTDIM / 4) / 256, 256>>>(out);
}

// round 13
// speedup vs baseline: 1.2112x; 1.0666x over previous
#include <cuda_runtime.h>
#include <cuda_bf16.h>
#include <cstdint>
#include <math.h>

#define BDIM   4096
#define INDIM  256
#define OUTDIM 256
#define NC     8
#define KDIM   (INDIM * NC)      // 2048
#define BPB    8                 // batch rows per build-thread

// ---------------- scratch (static device globals; no allocations) ----------
__device__ __nv_bfloat16 g_Bh[(size_t)OUTDIM * KDIM];      //  1 MB  B, [o][k]
__device__ __nv_bfloat16 g_A[(size_t)BDIM * KDIM];         // 16 MB  A, [b][k]
__device__ float g_rv[BDIM];                               // residual sums

// ---------------------------------------------------------------------------
// 1) merged build: blocks 0..255 build W^T; blocks 256..767 build A + rv
//    coefficient block computed ONCE per block (thread 0 -> shared)
// ---------------------------------------------------------------------------
__global__ __launch_bounds__(256) void build_AW_kernel(
    const float* __restrict__ coefs, const float* __restrict__ spline_scale,
    const float* __restrict__ x, const float* __restrict__ resid_scale,
    const float* __restrict__ aat) {
    const int tid = threadIdx.x;
    const int blk = blockIdx.x;

    if (blk < 256) {
        // ---- W: g_Bh[o][i*8+c] = bf16(spline_scale[i,o]*coefs[i,o,c]) ----
        int idx = blk * 256 + tid;  // i*256 + o
        int i = idx >> 8, o = idx & 255;
        float ss = spline_scale[idx];
        const float* cf = coefs + (size_t)idx * NC;
        uint4 uh;
        uint32_t* ph = (uint32_t*)&uh;
#pragma unroll
        for (int c = 0; c < 4; c++) {
            __nv_bfloat162 t = __floats2bfloat162_rn(ss * cf[2 * c], ss * cf[2 * c + 1]);
            ph[c] = *(uint32_t*)&t;
        }
        *(uint4*)&g_Bh[(size_t)o * KDIM + i * NC] = uh;
        return;
    }

    // ---- A: thread (blk,i=tid) handles b = b0..b0+7 of column i ----
    const int b0 = (blk - 256) * BPB;
    const int i  = tid;

    // x loads first (MLP=8 hides latency under the coeff computation)
    float xv[BPB];
#pragma unroll
    for (int p = 0; p < BPB; ++p)
        xv[p] = x[(size_t)(b0 + p) * INDIM + i];

    // coefficients once per block (12 IEEE divides in ONE thread, not 256)
    __shared__ float s_alpha, s_r1[NC], s_r2[NC];
    if (tid == 0) {
        float alpha = tanhf(__ldg(aat));
        s_alpha = alpha;
        for (int n = 2; n < NC; n++) {
            float c = 2.0f * n + 2.0f * alpha;
            float A = 2.0f * n * (n + 2.0f * alpha) * (c - 2.0f);
            s_r1[n] = (c - 1.0f) * c * (c - 2.0f) / A;
            s_r2[n] = 2.0f * (n + alpha - 1.0f) * (n + alpha - 1.0f) * c / A;
        }
    }
    __syncthreads();
    const float alpha = s_alpha;
    float r1[NC], r2[NC];
#pragma unroll
    for (int n = 2; n < NC; n++) { r1[n] = s_r1[n]; r2[n] = s_r2[n]; }
    const float rs = resid_scale[i];

    float rt[BPB];
#pragma unroll
    for (int p = 0; p < BPB; ++p) {
        float t = tanhf(xv[p]);
        rt[p] = rs * t;

        float pr[NC];
        pr[0] = 1.0f;
        pr[1] = (alpha + 1.0f) + (alpha + alpha + 2.0f) * (t - 1.0f) * 0.5f;
#pragma unroll
        for (int n = 2; n < NC; n++)
            pr[n] = r1[n] * t * pr[n - 1] - r2[n] * pr[n - 2];

        uint4 uh;
        uint32_t* ph = (uint32_t*)&uh;
#pragma unroll
        for (int c = 0; c < 4; c++) {
            __nv_bfloat162 t2 = __floats2bfloat162_rn(pr[2 * c], pr[2 * c + 1]);
            ph[c] = *(uint32_t*)&t2;
        }
        *(uint4*)&g_A[(size_t)(b0 + p) * KDIM + i * NC] = uh;
    }

    // rv reductions: for each p, sum rt[p] over the 256 i's of this block
    __shared__ float sred[8][BPB];    // [warp][p]
    const int wid = tid >> 5;
#pragma unroll
    for (int p = 0; p < BPB; ++p) {
        float v = rt[p];
#pragma unroll
        for (int off = 16; off > 0; off >>= 1)
            v += __shfl_down_sync(0xffffffffu, v, off);
        if ((tid & 31) == 0) sred[wid][p] = v;
    }
    __syncthreads();
    if (tid < BPB) {
        float v = 0.0f;
#pragma unroll
        for (int w = 0; w < 8; ++w) v += sred[w][tid];
        g_rv[b0 + tid] = v;
    }
}

// ---------------------------------------------------------------------------
// 2) GEMM, single-pass bf16, FULL K per CTA (no split) — direct epilogue
//    CTA 64x64, BK=64, 128 threads (4 warps, warp tile 32x32)
//    A and B: 3-deep cp.async rings, ONE __syncthreads per stage
// ---------------------------------------------------------------------------
#define BM 64
#define BN 64
#define BK 64
#define NTS (KDIM / BK)         // 32 k-chunks

#define ROWB 144                // 128B data + 16B pad
#define TILE_B (64 * ROWB)      // 9216 per tile
// layout: A0..A2 @0..2*TILE_B, B0..B2 @3..5*TILE_B
#define GEMM_SMEM (6 * TILE_B)  // 55296

__device__ __forceinline__ uint32_t smem_u32(const void* p) {
    uint32_t a;
    asm("{ .reg .u64 t; cvta.to.shared.u64 t, %1; cvt.u32.u64 %0, t; }"
        : "=r"(a) : "l"(p));
    return a;
}
__device__ __forceinline__ void cp16(uint32_t s, const void* g) {
    asm volatile("cp.async.cg.shared.global [%0], [%1], 16;" :: "r"(s), "l"(g));
}
__device__ __forceinline__ void ldsm_x4(uint32_t* r, uint32_t addr) {
    asm volatile("ldmatrix.sync.aligned.m8n8.x4.shared.b16 {%0,%1,%2,%3}, [%4];"
                 : "=r"(r[0]), "=r"(r[1]), "=r"(r[2]), "=r"(r[3]) : "r"(addr));
}
__device__ __forceinline__ void mma_bf16(float* d, const uint32_t* a, const uint32_t* b) {
    asm volatile(
        "mma.sync.aligned.m16n8k16.row.col.f32.bf16.bf16.f32 "
        "{%0,%1,%2,%3}, {%4,%5,%6,%7}, {%8,%9}, {%0,%1,%2,%3};"
        : "+f"(d[0]), "+f"(d[1]), "+f"(d[2]), "+f"(d[3])
        : "r"(a[0]), "r"(a[1]), "r"(a[2]), "r"(a[3]), "r"(b[0]), "r"(b[1]));
}

// prefetch A(kt) and B(kt) into ring slot (one commit group)
__device__ __forceinline__ void prefetch_AB(uint32_t sb, int slot, int kt,
                                            int m0, int n0, int tid) {
    const int k0 = kt * BK;
    const uint32_t dstA = sb + slot * TILE_B;
    const uint32_t dstB = sb + (3 + slot) * TILE_B;
#pragma unroll
    for (int p = 0; p < 4; ++p) {
        int idx = p * 128 + tid;           // 0..511
        int r = idx >> 3, c = idx & 7;
        cp16(dstA + r * ROWB + c * 16,
             g_A + (size_t)(m0 + r) * KDIM + k0 + c * 8);
        cp16(dstB + r * ROWB + c * 16,
             g_Bh + (size_t)(n0 + r) * KDIM + k0 + c * 8);
    }
    asm volatile("cp.async.commit_group;" ::: "memory");
}

__global__ __launch_bounds__(128, 4) void gemm_tc(float* __restrict__ out) {
    extern __shared__ char smem[];
    const int tid  = threadIdx.x;
    const int wid  = tid >> 5;
    const int lane = tid & 31;
    const int m0   = blockIdx.x * BM;
    const int n0   = blockIdx.y * BN;
    const int mbase = (wid & 1) * 32;
    const int nbase = (wid >> 1) * 32;
    const uint32_t sb = smem_u32(smem);

    float acc[2][4][4];
#pragma unroll
    for (int i = 0; i < 2; i++)
#pragma unroll
        for (int j = 0; j < 4; j++)
#pragma unroll
            for (int r = 0; r < 4; r++) acc[i][j][r] = 0.0f;

    // ldmatrix per-lane address pieces (mapping verified R3-R12)
    const int g  = lane >> 3;
    const int lr = lane & 7;
    const int a_row_off = lr + ((g & 1) ? 8 : 0);
    const int kb_off    = (g >= 2) ? 16 : 0;

    // prologue: stages 0 and 1
    prefetch_AB(sb, 0, 0, m0, n0, tid);
    prefetch_AB(sb, 1, 1, m0, n0, tid);
    asm volatile("cp.async.wait_group 1;" ::: "memory");
    __syncthreads();

#pragma unroll 4
    for (int kt = 0; kt < NTS; ++kt) {
        const int slot = kt % 3;
        const uint32_t stA = sb + slot * TILE_B;
        const uint32_t stB = sb + (3 + slot) * TILE_B;

        // ---- MMA phase on ring slot ----
#pragma unroll
        for (int ks = 0; ks < 4; ++ks) {
            uint32_t a[2][4], b[4][2];
#pragma unroll
            for (int mf = 0; mf < 2; ++mf) {
                uint32_t row = mbase + mf * 16 + a_row_off;
                ldsm_x4(a[mf], stA + row * ROWB + ks * 32 + kb_off);
            }
#pragma unroll
            for (int np = 0; np < 2; ++np) {
                uint32_t row = nbase + np * 16 + lr + ((g >= 2) ? 8 : 0);
                uint32_t kb2 = ks * 32 + ((g & 1) ? 16 : 0);
                uint32_t r4[4];
                ldsm_x4(r4, stB + row * ROWB + kb2);
                b[2 * np][0] = r4[0];     b[2 * np][1] = r4[1];
                b[2 * np + 1][0] = r4[2]; b[2 * np + 1][1] = r4[3];
            }
#pragma unroll
            for (int mf = 0; mf < 2; ++mf)
#pragma unroll
                for (int nf = 0; nf < 4; ++nf)
                    mma_bf16(acc[mf][nf], a[mf], b[nf]);
        }

        // ---- prefetch kt+2 into slot (kt+2)%3 (last read at kt-1; safe) ----
        if (kt + 2 < NTS) {
            prefetch_AB(sb, (kt + 2) % 3, kt + 2, m0, n0, tid);
            asm volatile("cp.async.wait_group 1;" ::: "memory");  // kt+1 done
        } else if (kt + 1 < NTS) {
            asm volatile("cp.async.wait_group 0;" ::: "memory");
        }

        if (kt + 1 < NTS) __syncthreads();   // single barrier per stage
    }

    // direct epilogue: out[m][n] = (acc + rv[m]) / IN
    const float sc = 1.0f / (float)INDIM;
    const int l4 = lane >> 2, l2 = (lane & 3) * 2;
#pragma unroll
    for (int mf = 0; mf < 2; ++mf) {
        int m = m0 + mbase + mf * 16 + l4;
        float rv0 = __ldg(&g_rv[m]);
        float rv1 = __ldg(&g_rv[m + 8]);
#pragma unroll
        for (int nf = 0; nf < 4; ++nf) {
            int n = n0 + nbase + nf * 8 + l2;
            *(float2*)&out[(size_t)m * OUTDIM + n] =
                make_float2((acc[mf][nf][0] + rv0) * sc,
                            (acc[mf][nf][1] + rv0) * sc);
            *(float2*)&out[(size_t)(m + 8) * OUTDIM + n] =
                make_float2((acc[mf][nf][2] + rv1) * sc,
                            (acc[mf][nf][3] + rv1) * sc);
        }
    }
}

// ---------------------------------------------------------------------------
extern "C" void kernel_launch(void* const* d_in, const int* in_sizes, int n_in,
                              void* d_out, int out_size) {
    const float *x = nullptr, *coefs = nullptr, *aat = nullptr;
    const float *resid_scale = nullptr, *spline_scale = nullptr;
    for (int i = 0; i < n_in; i++) {
        switch (in_sizes[i]) {
            case BDIM * INDIM:        x            = (const float*)d_in[i]; break;
            case INDIM * OUTDIM * NC: coefs        = (const float*)d_in[i]; break;
            case 1:                   aat          = (const float*)d_in[i]; break;
            case INDIM:               resid_scale  = (const float*)d_in[i]; break;
            case INDIM * OUTDIM:      spline_scale = (const float*)d_in[i]; break;
            default: break;
        }
    }
    float* out = (float*)d_out;

    cudaFuncSetAttribute(gemm_tc, cudaFuncAttributeMaxDynamicSharedMemorySize, GEMM_SMEM);

    build_AW_kernel<<<256 + BDIM / BPB, 256>>>(coefs, spline_scale, x, resid_scale, aat);
    dim3 grid(BDIM / BM, OUTDIM / BN);
    gemm_tc<<<grid, 128, GEMM_SMEM>>>(out);
}